// round 12
// baseline (speedup 1.0000x reference)
#include <cuda_runtime.h>
#include <cuda_bf16.h>
#include <cstdint>

// Problem constants
#define BB 64
#define TT 128
#define DD 512
#define HH 30
#define TM 98
static constexpr float INV_TEMP = 1.0f / 0.07f;

// Scratch (device globals: no allocation allowed)
__device__ __align__(16) __nv_bfloat16 g_zbf[BB * TT * DD];    // bf16 z_seq
__device__ __align__(16) __nv_bfloat16 g_cbf[BB * TT * DD];    // bf16 c_seq
__device__ __align__(16) __nv_bfloat16 g_cproj[BB * TT * DD];  // bf16 c_proj
__device__ __align__(16) __nv_bfloat16 g_Wt[DD * DD];          // bf16 W^T ([n][p])
__device__ float g_partials[TM * HH];

// ---------------------------------------------------------------------------
// PTX helpers
// ---------------------------------------------------------------------------
__device__ __forceinline__ uint32_t smem_u32(const void* p) {
    return (uint32_t)__cvta_generic_to_shared(p);
}
__device__ __forceinline__ void ldm_x4(uint32_t& a0, uint32_t& a1, uint32_t& a2,
                                       uint32_t& a3, uint32_t addr) {
    asm volatile("ldmatrix.sync.aligned.m8n8.x4.shared.b16 {%0,%1,%2,%3}, [%4];\n"
                 : "=r"(a0), "=r"(a1), "=r"(a2), "=r"(a3) : "r"(addr));
}
__device__ __forceinline__ void mma_bf16(float* c, uint32_t a0, uint32_t a1,
                                         uint32_t a2, uint32_t a3,
                                         uint32_t b0, uint32_t b1) {
    asm volatile(
        "mma.sync.aligned.m16n8k16.row.col.f32.bf16.bf16.f32 "
        "{%0,%1,%2,%3}, {%4,%5,%6,%7}, {%8,%9}, {%0,%1,%2,%3};\n"
        : "+f"(c[0]), "+f"(c[1]), "+f"(c[2]), "+f"(c[3])
        : "r"(a0), "r"(a1), "r"(a2), "r"(a3), "r"(b0), "r"(b1));
}
__device__ __forceinline__ void cp_async16(uint32_t dst, const void* src) {
    asm volatile("cp.async.ca.shared.global [%0], [%1], 16;\n" :: "r"(dst), "l"(src));
}
__device__ __forceinline__ void cp_commit() {
    asm volatile("cp.async.commit_group;\n");
}
template <int N>
__device__ __forceinline__ void cp_wait() {
    asm volatile("cp.async.wait_group %0;\n" :: "n"(N));
}

// ---------------------------------------------------------------------------
// Combined convert kernel: z fp32->bf16 | c fp32->bf16 | W transpose+convert
// grid: [0,4096) z, [4096,8192) c, [8192,9216) W
// ---------------------------------------------------------------------------
__global__ void k_convert_all(const float* __restrict__ z, const float* __restrict__ c,
                              const float* __restrict__ W) {
    int b = blockIdx.x;
    int tid = threadIdx.x;
    if (b < 8192) {
        const float* src = (b < 4096) ? z : c;
        __nv_bfloat16* dst = (b < 4096) ? g_zbf : g_cbf;
        int idx = (((b & 4095) * 256) + tid) * 4;
        float4 v = *(const float4*)(src + idx);
        *(__nv_bfloat162*)(dst + idx) = __floats2bfloat162_rn(v.x, v.y);
        *(__nv_bfloat162*)(dst + idx + 2) = __floats2bfloat162_rn(v.z, v.w);
    } else {
        int i = (b - 8192) * 256 + tid;     // 0 .. 262143
        int n = i >> 9;
        int p = i & 511;
        g_Wt[i] = __float2bfloat16(W[p * DD + n]);
    }
}

// ---------------------------------------------------------------------------
// GEMM1: c_proj = c @ W + b.  M=8192, N=512, K=512.  (exact R6 version)
// CTA tile 128x128, 256 thr (8 warps, warp tile 32x64), K-chunk 64, 2-stage.
// ---------------------------------------------------------------------------
#define G1_LD 72
#define G1_TILE_B (128 * G1_LD * 2)      // 18432
#define G1_STAGE_B (2 * G1_TILE_B)      // 36864
#define G1_SMEM (2 * G1_STAGE_B)        // 73728 -> 2 CTAs/SM

__global__ __launch_bounds__(256) void k_gemm1(const float* __restrict__ bias) {
    extern __shared__ char sm[];
    const int tid = threadIdx.x;
    const int w = tid >> 5;
    const int lane = tid & 31;
    const int wr = w >> 1;
    const int wc = w & 1;
    const int g = lane >> 2;
    const int t4 = lane & 3;
    const int m0 = blockIdx.x * 128;
    const int n0 = blockIdx.y * 128;

    float acc[2][8][4];
#pragma unroll
    for (int a = 0; a < 2; a++)
#pragma unroll
        for (int nt = 0; nt < 8; nt++)
#pragma unroll
            for (int e = 0; e < 4; e++) acc[a][nt][e] = 0.f;

    auto issue = [&](int kc, int st) {
        char* base = sm + st * G1_STAGE_B;
        uint32_t sa = smem_u32(base);
        uint32_t sb = sa + G1_TILE_B;
#pragma unroll
        for (int it = 0; it < 4; it++) {
            int idx = tid + it * 256;
            int r = idx >> 3, cu = idx & 7;
            cp_async16(sa + (r * G1_LD + cu * 8) * 2,
                       g_cbf + (size_t)(m0 + r) * DD + kc * 64 + cu * 8);
        }
#pragma unroll
        for (int it = 0; it < 4; it++) {
            int idx = tid + it * 256;
            int r = idx >> 3, cu = idx & 7;
            cp_async16(sb + (r * G1_LD + cu * 8) * 2,
                       g_Wt + (size_t)(n0 + r) * DD + kc * 64 + cu * 8);
        }
        cp_commit();
    };

    issue(0, 0);

    for (int kc = 0; kc < 8; kc++) {
        if (kc < 7) issue(kc + 1, (kc + 1) & 1);
        if (kc < 7) cp_wait<1>(); else cp_wait<0>();
        __syncthreads();
        char* base = sm + (kc & 1) * G1_STAGE_B;
        uint32_t sa = smem_u32(base);
        uint32_t sb = sa + G1_TILE_B;
#pragma unroll
        for (int ks = 0; ks < 4; ks++) {
            uint32_t af[2][4];
#pragma unroll
            for (int a = 0; a < 2; a++) {
                uint32_t addr = sa + ((wr * 32 + a * 16 + (lane & 15)) * G1_LD +
                                      ks * 16 + (lane >> 4) * 8) * 2;
                ldm_x4(af[a][0], af[a][1], af[a][2], af[a][3], addr);
            }
#pragma unroll
            for (int np = 0; np < 4; np++) {
                uint32_t b0, b1, b2, b3;
                uint32_t addr = sb + ((wc * 64 + np * 16 + ((lane >> 4) & 1) * 8 +
                                       (lane & 7)) * G1_LD +
                                      ks * 16 + ((lane >> 3) & 1) * 8) * 2;
                ldm_x4(b0, b1, b2, b3, addr);
#pragma unroll
                for (int a = 0; a < 2; a++) {
                    mma_bf16(acc[a][2 * np], af[a][0], af[a][1], af[a][2], af[a][3], b0, b1);
                    mma_bf16(acc[a][2 * np + 1], af[a][0], af[a][1], af[a][2], af[a][3], b2, b3);
                }
            }
        }
        __syncthreads();
    }

#pragma unroll
    for (int a = 0; a < 2; a++) {
        int r0 = m0 + wr * 32 + a * 16 + g;
#pragma unroll
        for (int nt = 0; nt < 8; nt++) {
            int col = n0 + wc * 64 + nt * 8 + t4 * 2;
            float bv0 = bias[col], bv1 = bias[col + 1];
            *(__nv_bfloat162*)(g_cproj + (size_t)r0 * DD + col) =
                __floats2bfloat162_rn(acc[a][nt][0] + bv0, acc[a][nt][1] + bv1);
            *(__nv_bfloat162*)(g_cproj + (size_t)(r0 + 8) * DD + col) =
                __floats2bfloat162_rn(acc[a][nt][2] + bv0, acc[a][nt][3] + bv1);
        }
    }
}

// ---------------------------------------------------------------------------
// Fused scores + LSE - diag, diagonal-block, 64x64 warp tiles.
// Grid (49, 3): CTA = (t-pair {t0,t0+1}, s-window). 256 thr, 8 warps.
// C pair resident (M=128 x K=512, ld 520). Phase = 4 s-slots x 2 warps;
// warp tile 64x64 (full t-block rows). LDSM:MMA = 0.25.
// Z streamed in 64-col K-chunks (4 slots/chunk), 2-stage double buffer
// (8 slots x 9216 B). 8 chunks per phase -> 4 syncs per s-tile (as R6).
// ---------------------------------------------------------------------------
#define SC_LD 520
#define SC_BYTES (128 * SC_LD * 2)       // 133120
#define SZ_LD 72
#define SZ_SLOT (64 * SZ_LD * 2)         // 9216
#define SZ_BYTES (8 * SZ_SLOT)           // 73728 (2 stages x 4 slots)
#define S_SMEM (SC_BYTES + SZ_BYTES + 64)  // 206912

__global__ __launch_bounds__(256) void k_scores() {
    extern __shared__ char sm[];
    uint32_t sC = smem_u32(sm);
    uint32_t sZ0 = sC + SC_BYTES;
    float* sRed = (float*)(sm + SC_BYTES + SZ_BYTES);

    const int t0 = blockIdx.x * 2;
    const int y = blockIdx.y;
    const int s_base = t0 + 1 + ((y == 0) ? 0 : (y == 1) ? 11 : 21);
    const int win = (y == 0) ? 11 : 10;
    const int P = (win + 3) >> 2;       // 3 phases: {4,4,3} or {4,4,2}
    const int ITERS = 8 * P;            // 8 x 64-col K-chunks per phase

    const int tid = threadIdx.x;
    const int w = tid >> 5;
    const int lane = tid & 31;
    const int slot = w >> 1;            // s-slot within phase (0..3)
    const int wh = w & 1;               // M-half: rows wh*64..+64 (t0 / t0+1)
    const int g = lane >> 2;
    const int t4 = lane & 3;

    // --- Prologue: C tiles for t0 and t0+1 (rows 0-63 / 64-127), group 0 ---
#pragma unroll
    for (int it = 0; it < 32; it++) {
        int idx = tid + it * 256;           // 0..8191 -> 128 rows x 64 uint4
        int r = idx >> 6, cu = idx & 63;
        int i = r & 63, tt = t0 + (r >> 6);
        cp_async16(sC + (r * SC_LD + cu * 8) * 2,
                   g_cproj + ((size_t)i * TT + tt) * DD + cu * 8);
    }
    cp_commit();

    auto issue_z = [&](int j) {
        int p = j >> 3, ch = j & 7;
#pragma unroll
        for (int sl = 0; sl < 4; sl++) {
            if (p * 4 + sl >= win) break;
            int s = s_base + p * 4 + sl;
            uint32_t dst = sZ0 + (uint32_t)((j & 1) * 4 + sl) * SZ_SLOT;
#pragma unroll
            for (int it2 = 0; it2 < 2; it2++) {
                int idx = tid + it2 * 256;  // 0..511 -> 64 rows x 8 uint4
                int rr = idx >> 3, cc = idx & 7;
                cp_async16(dst + (rr * SZ_LD + cc * 8) * 2,
                           g_zbf + ((size_t)rr * TT + s) * DD + ch * 64 + cc * 8);
            }
        }
        cp_commit();
    };

    issue_z(0);     // group 1
    issue_z(1);     // group 2
    cp_wait<1>();   // C + chunk0 ready
    __syncthreads();

    float acc[4][8][4];
#pragma unroll
    for (int a = 0; a < 4; a++)
#pragma unroll
        for (int nt = 0; nt < 8; nt++)
#pragma unroll
            for (int e = 0; e < 4; e++) acc[a][nt][e] = 0.f;

    for (int it = 0; it < ITERS; it++) {
        const int p = it >> 3, ch = it & 7;
        const bool slot_active = (p * 4 + slot) < win;

        // --- Compute this 64-col K-chunk: warp tile 64x64 ---
        if (slot_active) {
            uint32_t sz = sZ0 + (uint32_t)((it & 1) * 4 + slot) * SZ_SLOT;
#pragma unroll
            for (int ks = 0; ks < 4; ks++) {
                uint32_t af[4][4];
#pragma unroll
                for (int a = 0; a < 4; a++) {
                    uint32_t addr = sC + ((wh * 64 + a * 16 + (lane & 15)) * SC_LD +
                                          ch * 64 + ks * 16 + (lane >> 4) * 8) * 2;
                    ldm_x4(af[a][0], af[a][1], af[a][2], af[a][3], addr);
                }
#pragma unroll
                for (int np = 0; np < 4; np++) {
                    uint32_t b0, b1, b2, b3;
                    uint32_t addr = sz + ((np * 16 + ((lane >> 4) & 1) * 8 +
                                           (lane & 7)) * SZ_LD +
                                          ks * 16 + ((lane >> 3) & 1) * 8) * 2;
                    ldm_x4(b0, b1, b2, b3, addr);
#pragma unroll
                    for (int a = 0; a < 4; a++) {
                        mma_bf16(acc[a][2 * np], af[a][0], af[a][1], af[a][2], af[a][3], b0, b1);
                        mma_bf16(acc[a][2 * np + 1], af[a][0], af[a][1], af[a][2], af[a][3], b2, b3);
                    }
                }
            }
        }
        __syncthreads();                    // stage fully consumed

        if (it + 2 < ITERS) issue_z(it + 2);

        // --- End of phase: LSE - diag epilogue ---
        if (ch == 7) {
            const int s = s_base + p * 4 + slot;
            const int k = s - (t0 + wh);
            const bool valid = slot_active && (k >= 1) && (k <= 30);

            float local = 0.f;
            if (valid) {
#pragma unroll
                for (int a = 0; a < 4; a++) {
#pragma unroll
                    for (int rp = 0; rp < 2; rp++) {
                        const int e0 = rp * 2;
                        float m = -3.4e38f;
#pragma unroll
                        for (int nt = 0; nt < 8; nt++)
                            m = fmaxf(m, fmaxf(acc[a][nt][e0], acc[a][nt][e0 + 1]));
                        m = fmaxf(m, __shfl_xor_sync(0xffffffffu, m, 1));
                        m = fmaxf(m, __shfl_xor_sync(0xffffffffu, m, 2));
                        float se = 0.f;
#pragma unroll
                        for (int nt = 0; nt < 8; nt++) {
                            se += expf((acc[a][nt][e0] - m) * INV_TEMP);
                            se += expf((acc[a][nt][e0 + 1] - m) * INV_TEMP);
                        }
                        se += __shfl_xor_sync(0xffffffffu, se, 1);
                        se += __shfl_xor_sync(0xffffffffu, se, 2);
                        float lse = m * INV_TEMP + logf(se);
                        int j = a * 16 + rp * 8 + g;             // 0..63 diag col
                        if (t4 == ((j >> 1) & 3))
                            local += lse - acc[a][j >> 3][e0 + (j & 1)] * INV_TEMP;
                    }
                }
            }
#pragma unroll
            for (int off = 16; off > 0; off >>= 1)
                local += __shfl_xor_sync(0xffffffffu, local, off);
            if (lane == 0) sRed[w] = local;
            __syncthreads();
            // sRed[w]: w = slot*2 + half; warp covers full 64-row t-block
            if (tid < 8) {
                int wsl = tid >> 1, half = tid & 1;
                if (p * 4 + wsl < win) {
                    int ss = s_base + p * 4 + wsl;
                    int tt = t0 + half;
                    int kk = ss - tt;
                    if (kk >= 1 && kk <= 30)
                        g_partials[tt * HH + kk - 1] = sRed[wsl * 2 + half];
                }
            }
            // zero accumulators for next phase
#pragma unroll
            for (int a = 0; a < 4; a++)
#pragma unroll
                for (int nt = 0; nt < 8; nt++)
#pragma unroll
                    for (int e = 0; e < 4; e++) acc[a][nt][e] = 0.f;
        }

        if (it + 1 < ITERS) {
            if (it + 2 < ITERS) cp_wait<1>(); else cp_wait<0>();
            __syncthreads();                // next stage ready
        }
    }
}

// ---------------------------------------------------------------------------
// Final deterministic reduction
// ---------------------------------------------------------------------------
__global__ void k_reduce(float* __restrict__ out) {
    __shared__ float sh[256];
    int tid = threadIdx.x;
    float ssum = 0.f;
    for (int i = tid; i < TM * HH; i += 256) ssum += g_partials[i];
    sh[tid] = ssum;
    __syncthreads();
    for (int off = 128; off > 0; off >>= 1) {
        if (tid < off) sh[tid] += sh[tid + off];
        __syncthreads();
    }
    if (tid == 0) out[0] = sh[0] / (float)(TM * HH * BB);
}

// ---------------------------------------------------------------------------
extern "C" void kernel_launch(void* const* d_in, const int* in_sizes, int n_in,
                              void* d_out, int out_size) {
    const float* z = (const float*)d_in[0];
    const float* c = (const float*)d_in[1];
    const float* W = (const float*)d_in[2];
    const float* bias = (const float*)d_in[3];
    float* out = (float*)d_out;
    (void)in_sizes; (void)n_in; (void)out_size;

    cudaFuncSetAttribute(k_scores, cudaFuncAttributeMaxDynamicSharedMemorySize, S_SMEM);
    cudaFuncSetAttribute(k_gemm1, cudaFuncAttributeMaxDynamicSharedMemorySize, G1_SMEM);

    k_convert_all<<<9216, 256>>>(z, c, W);
    k_gemm1<<<dim3(64, 4), 256, G1_SMEM>>>(bias);
    k_scores<<<dim3(49, 3), 256, S_SMEM>>>();
    k_reduce<<<1, 256>>>(out);
}

// round 14
// speedup vs baseline: 2.6530x; 2.6530x over previous
#include <cuda_runtime.h>
#include <cuda_bf16.h>
#include <cstdint>

// Problem constants
#define BB 64
#define TT 128
#define DD 512
#define HH 30
#define TM 98
static constexpr float INV_TEMP = 1.0f / 0.07f;

// Scratch (device globals: no allocation allowed)
__device__ __align__(16) __nv_bfloat16 g_zbf[BB * TT * DD];    // bf16 z_seq
__device__ __align__(16) __nv_bfloat16 g_cbf[BB * TT * DD];    // bf16 c_seq
__device__ __align__(16) __nv_bfloat16 g_cproj[BB * TT * DD];  // bf16 c_proj
__device__ __align__(16) __nv_bfloat16 g_Wt[DD * DD];          // bf16 W^T ([n][p])
__device__ float g_partials[TM * HH];

// ---------------------------------------------------------------------------
// PTX helpers
// ---------------------------------------------------------------------------
__device__ __forceinline__ uint32_t smem_u32(const void* p) {
    return (uint32_t)__cvta_generic_to_shared(p);
}
__device__ __forceinline__ void ldm_x4(uint32_t& a0, uint32_t& a1, uint32_t& a2,
                                       uint32_t& a3, uint32_t addr) {
    asm volatile("ldmatrix.sync.aligned.m8n8.x4.shared.b16 {%0,%1,%2,%3}, [%4];\n"
                 : "=r"(a0), "=r"(a1), "=r"(a2), "=r"(a3) : "r"(addr));
}
__device__ __forceinline__ void mma_bf16(float* c, uint32_t a0, uint32_t a1,
                                         uint32_t a2, uint32_t a3,
                                         uint32_t b0, uint32_t b1) {
    asm volatile(
        "mma.sync.aligned.m16n8k16.row.col.f32.bf16.bf16.f32 "
        "{%0,%1,%2,%3}, {%4,%5,%6,%7}, {%8,%9}, {%0,%1,%2,%3};\n"
        : "+f"(c[0]), "+f"(c[1]), "+f"(c[2]), "+f"(c[3])
        : "r"(a0), "r"(a1), "r"(a2), "r"(a3), "r"(b0), "r"(b1));
}
__device__ __forceinline__ void cp_async16(uint32_t dst, const void* src) {
    asm volatile("cp.async.ca.shared.global [%0], [%1], 16;\n" :: "r"(dst), "l"(src));
}
__device__ __forceinline__ void cp_commit() {
    asm volatile("cp.async.commit_group;\n");
}
template <int N>
__device__ __forceinline__ void cp_wait() {
    asm volatile("cp.async.wait_group %0;\n" :: "n"(N));
}

// ---------------------------------------------------------------------------
// Combined convert kernel: z fp32->bf16 | c fp32->bf16 | W transpose+convert
// grid: [0,4096) z, [4096,8192) c, [8192,9216) W
// ---------------------------------------------------------------------------
__global__ void k_convert_all(const float* __restrict__ z, const float* __restrict__ c,
                              const float* __restrict__ W) {
    int b = blockIdx.x;
    int tid = threadIdx.x;
    if (b < 8192) {
        const float* src = (b < 4096) ? z : c;
        __nv_bfloat16* dst = (b < 4096) ? g_zbf : g_cbf;
        int idx = (((b & 4095) * 256) + tid) * 4;
        float4 v = *(const float4*)(src + idx);
        *(__nv_bfloat162*)(dst + idx) = __floats2bfloat162_rn(v.x, v.y);
        *(__nv_bfloat162*)(dst + idx + 2) = __floats2bfloat162_rn(v.z, v.w);
    } else {
        int i = (b - 8192) * 256 + tid;     // 0 .. 262143
        int n = i >> 9;
        int p = i & 511;
        g_Wt[i] = __float2bfloat16(W[p * DD + n]);
    }
}

// ---------------------------------------------------------------------------
// GEMM1: c_proj = c @ W + b.  M=8192, N=512, K=512.  (exact R6 version)
// CTA tile 128x128, 256 thr (8 warps, warp tile 32x64), K-chunk 64, 2-stage.
// ---------------------------------------------------------------------------
#define G1_LD 72
#define G1_TILE_B (128 * G1_LD * 2)      // 18432
#define G1_STAGE_B (2 * G1_TILE_B)      // 36864
#define G1_SMEM (2 * G1_STAGE_B)        // 73728 -> 2 CTAs/SM

__global__ __launch_bounds__(256) void k_gemm1(const float* __restrict__ bias) {
    extern __shared__ char sm[];
    const int tid = threadIdx.x;
    const int w = tid >> 5;
    const int lane = tid & 31;
    const int wr = w >> 1;
    const int wc = w & 1;
    const int g = lane >> 2;
    const int t4 = lane & 3;
    const int m0 = blockIdx.x * 128;
    const int n0 = blockIdx.y * 128;

    float acc[2][8][4];
#pragma unroll
    for (int a = 0; a < 2; a++)
#pragma unroll
        for (int nt = 0; nt < 8; nt++)
#pragma unroll
            for (int e = 0; e < 4; e++) acc[a][nt][e] = 0.f;

    auto issue = [&](int kc, int st) {
        char* base = sm + st * G1_STAGE_B;
        uint32_t sa = smem_u32(base);
        uint32_t sb = sa + G1_TILE_B;
#pragma unroll
        for (int it = 0; it < 4; it++) {
            int idx = tid + it * 256;
            int r = idx >> 3, cu = idx & 7;
            cp_async16(sa + (r * G1_LD + cu * 8) * 2,
                       g_cbf + (size_t)(m0 + r) * DD + kc * 64 + cu * 8);
        }
#pragma unroll
        for (int it = 0; it < 4; it++) {
            int idx = tid + it * 256;
            int r = idx >> 3, cu = idx & 7;
            cp_async16(sb + (r * G1_LD + cu * 8) * 2,
                       g_Wt + (size_t)(n0 + r) * DD + kc * 64 + cu * 8);
        }
        cp_commit();
    };

    issue(0, 0);

    for (int kc = 0; kc < 8; kc++) {
        if (kc < 7) issue(kc + 1, (kc + 1) & 1);
        if (kc < 7) cp_wait<1>(); else cp_wait<0>();
        __syncthreads();
        char* base = sm + (kc & 1) * G1_STAGE_B;
        uint32_t sa = smem_u32(base);
        uint32_t sb = sa + G1_TILE_B;
#pragma unroll
        for (int ks = 0; ks < 4; ks++) {
            uint32_t af[2][4];
#pragma unroll
            for (int a = 0; a < 2; a++) {
                uint32_t addr = sa + ((wr * 32 + a * 16 + (lane & 15)) * G1_LD +
                                      ks * 16 + (lane >> 4) * 8) * 2;
                ldm_x4(af[a][0], af[a][1], af[a][2], af[a][3], addr);
            }
#pragma unroll
            for (int np = 0; np < 4; np++) {
                uint32_t b0, b1, b2, b3;
                uint32_t addr = sb + ((wc * 64 + np * 16 + ((lane >> 4) & 1) * 8 +
                                       (lane & 7)) * G1_LD +
                                      ks * 16 + ((lane >> 3) & 1) * 8) * 2;
                ldm_x4(b0, b1, b2, b3, addr);
#pragma unroll
                for (int a = 0; a < 2; a++) {
                    mma_bf16(acc[a][2 * np], af[a][0], af[a][1], af[a][2], af[a][3], b0, b1);
                    mma_bf16(acc[a][2 * np + 1], af[a][0], af[a][1], af[a][2], af[a][3], b2, b3);
                }
            }
        }
        __syncthreads();
    }

#pragma unroll
    for (int a = 0; a < 2; a++) {
        int r0 = m0 + wr * 32 + a * 16 + g;
#pragma unroll
        for (int nt = 0; nt < 8; nt++) {
            int col = n0 + wc * 64 + nt * 8 + t4 * 2;
            float bv0 = bias[col], bv1 = bias[col + 1];
            *(__nv_bfloat162*)(g_cproj + (size_t)r0 * DD + col) =
                __floats2bfloat162_rn(acc[a][nt][0] + bv0, acc[a][nt][1] + bv1);
            *(__nv_bfloat162*)(g_cproj + (size_t)(r0 + 8) * DD + col) =
                __floats2bfloat162_rn(acc[a][nt][2] + bv0, acc[a][nt][3] + bv1);
        }
    }
}

// ---------------------------------------------------------------------------
// Fused scores + LSE - diag, diagonal-block version (EXACT R6 = best 112.6us).
// Grid (49, 3): CTA = (t-pair {t0,t0+1}, s-window). 256 thr, 8 warps.
// C pair resident (M=128 x K=512, ld 520). Phase = 2 s-slots x 4 warps,
// warp tile 32x64. Z streamed in 128-col D-chunks, 2-stage x 2 slots.
// ---------------------------------------------------------------------------
#define SC_LD 520
#define SC_BYTES (128 * SC_LD * 2)       // 133120
#define SZ_LD 136
#define SZ_SLOT (64 * SZ_LD * 2)         // 17408
#define SZ_BYTES (4 * SZ_SLOT)           // 69632
#define S_SMEM (SC_BYTES + SZ_BYTES + 64)  // 202816

__global__ __launch_bounds__(256) void k_scores() {
    extern __shared__ char sm[];
    uint32_t sC = smem_u32(sm);
    uint32_t sZ0 = sC + SC_BYTES;
    float* sRed = (float*)(sm + SC_BYTES + SZ_BYTES);

    const int t0 = blockIdx.x * 2;
    const int y = blockIdx.y;
    const int s_base = t0 + 1 + ((y == 0) ? 0 : (y == 1) ? 11 : 21);
    const int win = (y == 0) ? 11 : 10;
    const int P = (win + 1) >> 1;       // phases (2 s per phase; last may be 1)
    const int ITERS = 4 * P;

    const int tid = threadIdx.x;
    const int w = tid >> 5;
    const int lane = tid & 31;
    const int slot = w >> 2;            // s-slot within phase (0/1)
    const int wr = w & 3;               // row quarter: rows wr*32..+32 of M=128
    const int g = lane >> 2;
    const int t4 = lane & 3;

    // --- Prologue: C tiles for t0 and t0+1 (rows 0-63 / 64-127) ---
#pragma unroll
    for (int it = 0; it < 32; it++) {
        int idx = tid + it * 256;           // 0..8191 -> 128 rows x 64 uint4
        int r = idx >> 6, cu = idx & 63;
        int i = r & 63, tt = t0 + (r >> 6);
        cp_async16(sC + (r * SC_LD + cu * 8) * 2,
                   g_cproj + ((size_t)i * TT + tt) * DD + cu * 8);
    }
    cp_commit();

    auto issue_z = [&](int it) {
        int p = it >> 2, ch = it & 3, st = it & 1;
#pragma unroll
        for (int sl = 0; sl < 2; sl++) {
            if (2 * p + sl >= win) break;
            int s = s_base + 2 * p + sl;
            uint32_t dst = sZ0 + (uint32_t)(st * 2 + sl) * SZ_SLOT;
#pragma unroll
            for (int j = 0; j < 4; j++) {
                int idx = tid + j * 256;    // 0..1023 -> 64 rows x 16 uint4
                int r = idx >> 4, cu = idx & 15;
                cp_async16(dst + (r * SZ_LD + cu * 8) * 2,
                           g_zbf + ((size_t)r * TT + s) * DD + ch * 128 + cu * 8);
            }
        }
        cp_commit();
    };

    issue_z(0);
    issue_z(1);
    cp_wait<1>();       // C + stage0 ready
    __syncthreads();

    float acc[2][8][4];
#pragma unroll
    for (int a = 0; a < 2; a++)
#pragma unroll
        for (int nt = 0; nt < 8; nt++)
#pragma unroll
            for (int e = 0; e < 4; e++) acc[a][nt][e] = 0.f;

    for (int it = 0; it < ITERS; it++) {
        const int p = it >> 2, ch = it & 3;
        const bool slot_active = (2 * p + slot) < win;

        // --- Compute this D-chunk ---
        if (slot_active) {
            uint32_t sz = sZ0 + (uint32_t)((it & 1) * 2 + slot) * SZ_SLOT;
#pragma unroll
            for (int ks = 0; ks < 8; ks++) {
                uint32_t af[2][4];
#pragma unroll
                for (int a = 0; a < 2; a++) {
                    uint32_t addr = sC + ((wr * 32 + a * 16 + (lane & 15)) * SC_LD +
                                          ch * 128 + ks * 16 + (lane >> 4) * 8) * 2;
                    ldm_x4(af[a][0], af[a][1], af[a][2], af[a][3], addr);
                }
#pragma unroll
                for (int np = 0; np < 4; np++) {
                    uint32_t b0, b1, b2, b3;
                    uint32_t addr = sz + ((np * 16 + ((lane >> 4) & 1) * 8 +
                                           (lane & 7)) * SZ_LD +
                                          ks * 16 + ((lane >> 3) & 1) * 8) * 2;
                    ldm_x4(b0, b1, b2, b3, addr);
#pragma unroll
                    for (int a = 0; a < 2; a++) {
                        mma_bf16(acc[a][2 * np], af[a][0], af[a][1], af[a][2], af[a][3], b0, b1);
                        mma_bf16(acc[a][2 * np + 1], af[a][0], af[a][1], af[a][2], af[a][3], b2, b3);
                    }
                }
            }
        }
        __syncthreads();                    // stage fully consumed

        if (it + 2 < ITERS) issue_z(it + 2);

        // --- End of phase: LSE - diag epilogue ---
        if (ch == 3) {
            const int s = s_base + 2 * p + slot;
            const int th = wr >> 1;         // row half: 0 -> t0, 1 -> t0+1
            const int tcur = t0 + th;
            const int k = s - tcur;
            const bool valid = slot_active && (k >= 1) && (k <= 30);

            float local = 0.f;
            if (valid) {
#pragma unroll
                for (int a = 0; a < 2; a++) {
#pragma unroll
                    for (int rp = 0; rp < 2; rp++) {
                        const int e0 = rp * 2;
                        float m = -3.4e38f;
#pragma unroll
                        for (int nt = 0; nt < 8; nt++)
                            m = fmaxf(m, fmaxf(acc[a][nt][e0], acc[a][nt][e0 + 1]));
                        m = fmaxf(m, __shfl_xor_sync(0xffffffffu, m, 1));
                        m = fmaxf(m, __shfl_xor_sync(0xffffffffu, m, 2));
                        float se = 0.f;
#pragma unroll
                        for (int nt = 0; nt < 8; nt++) {
                            se += expf((acc[a][nt][e0] - m) * INV_TEMP);
                            se += expf((acc[a][nt][e0 + 1] - m) * INV_TEMP);
                        }
                        se += __shfl_xor_sync(0xffffffffu, se, 1);
                        se += __shfl_xor_sync(0xffffffffu, se, 2);
                        float lse = m * INV_TEMP + logf(se);
                        int r = wr * 32 + a * 16 + rp * 8 + g;   // 0..127
                        int j = r & 63;                          // diag col
                        if (t4 == ((j >> 1) & 3))
                            local += lse - acc[a][j >> 3][e0 + (j & 1)] * INV_TEMP;
                    }
                }
            }
#pragma unroll
            for (int off = 16; off > 0; off >>= 1)
                local += __shfl_xor_sync(0xffffffffu, local, off);
            if (lane == 0) sRed[w] = local;
            __syncthreads();
            // sRed[w]: w = slot*4 + half*2 + {0,1}
            if (tid < 4) {
                int wsl = tid >> 1, half = tid & 1;
                if (2 * p + wsl < win) {
                    int ss = s_base + 2 * p + wsl;
                    int tt = t0 + half;
                    int kk = ss - tt;
                    if (kk >= 1 && kk <= 30)
                        g_partials[tt * HH + kk - 1] =
                            sRed[wsl * 4 + half * 2] + sRed[wsl * 4 + half * 2 + 1];
                }
            }
            // zero accumulators for next phase
#pragma unroll
            for (int a = 0; a < 2; a++)
#pragma unroll
                for (int nt = 0; nt < 8; nt++)
#pragma unroll
                    for (int e = 0; e < 4; e++) acc[a][nt][e] = 0.f;
        }

        if (it + 1 < ITERS) {
            if (it + 2 < ITERS) cp_wait<1>(); else cp_wait<0>();
            __syncthreads();                // next stage ready
        }
    }
}

// ---------------------------------------------------------------------------
// Final deterministic reduction — 1024 threads, two-level warp reduce.
// ---------------------------------------------------------------------------
__global__ void k_reduce(float* __restrict__ out) {
    __shared__ float sh[32];
    int tid = threadIdx.x;
    float ssum = 0.f;
#pragma unroll
    for (int i = 0; i < 3; i++) {
        int idx = tid + i * 1024;
        if (idx < TM * HH) ssum += g_partials[idx];
    }
#pragma unroll
    for (int off = 16; off > 0; off >>= 1)
        ssum += __shfl_xor_sync(0xffffffffu, ssum, off);
    if ((tid & 31) == 0) sh[tid >> 5] = ssum;
    __syncthreads();
    if (tid < 32) {
        float v = sh[tid];
#pragma unroll
        for (int off = 16; off > 0; off >>= 1)
            v += __shfl_xor_sync(0xffffffffu, v, off);
        if (tid == 0) out[0] = v / (float)(TM * HH * BB);
    }
}

// ---------------------------------------------------------------------------
extern "C" void kernel_launch(void* const* d_in, const int* in_sizes, int n_in,
                              void* d_out, int out_size) {
    const float* z = (const float*)d_in[0];
    const float* c = (const float*)d_in[1];
    const float* W = (const float*)d_in[2];
    const float* bias = (const float*)d_in[3];
    float* out = (float*)d_out;
    (void)in_sizes; (void)n_in; (void)out_size;

    cudaFuncSetAttribute(k_scores, cudaFuncAttributeMaxDynamicSharedMemorySize, S_SMEM);
    cudaFuncSetAttribute(k_gemm1, cudaFuncAttributeMaxDynamicSharedMemorySize, G1_SMEM);

    k_convert_all<<<9216, 256>>>(z, c, W);
    k_gemm1<<<dim3(64, 4), 256, G1_SMEM>>>(bias);
    k_scores<<<dim3(49, 3), 256, S_SMEM>>>();
    k_reduce<<<1, 1024>>>(out);
}

// round 15
// speedup vs baseline: 2.6538x; 1.0003x over previous
#include <cuda_runtime.h>
#include <cuda_bf16.h>
#include <cstdint>

// Problem constants
#define BB 64
#define TT 128
#define DD 512
#define HH 30
#define TM 98
static constexpr float INV_TEMP = 1.0f / 0.07f;

// Scratch (device globals: no allocation allowed)
__device__ __align__(16) __nv_bfloat16 g_zbf[BB * TT * DD];    // bf16 z_seq
__device__ __align__(16) __nv_bfloat16 g_cbf[BB * TT * DD];    // bf16 c_seq
__device__ __align__(16) __nv_bfloat16 g_cproj[BB * TT * DD];  // bf16 c_proj
__device__ __align__(16) __nv_bfloat16 g_Wt[DD * DD];          // bf16 W^T ([n][p])
__device__ float g_partials[TM * HH];

// ---------------------------------------------------------------------------
// PTX helpers
// ---------------------------------------------------------------------------
__device__ __forceinline__ uint32_t smem_u32(const void* p) {
    return (uint32_t)__cvta_generic_to_shared(p);
}
__device__ __forceinline__ void ldm_x4(uint32_t& a0, uint32_t& a1, uint32_t& a2,
                                       uint32_t& a3, uint32_t addr) {
    asm volatile("ldmatrix.sync.aligned.m8n8.x4.shared.b16 {%0,%1,%2,%3}, [%4];\n"
                 : "=r"(a0), "=r"(a1), "=r"(a2), "=r"(a3) : "r"(addr));
}
__device__ __forceinline__ void mma_bf16(float* c, uint32_t a0, uint32_t a1,
                                         uint32_t a2, uint32_t a3,
                                         uint32_t b0, uint32_t b1) {
    asm volatile(
        "mma.sync.aligned.m16n8k16.row.col.f32.bf16.bf16.f32 "
        "{%0,%1,%2,%3}, {%4,%5,%6,%7}, {%8,%9}, {%0,%1,%2,%3};\n"
        : "+f"(c[0]), "+f"(c[1]), "+f"(c[2]), "+f"(c[3])
        : "r"(a0), "r"(a1), "r"(a2), "r"(a3), "r"(b0), "r"(b1));
}
__device__ __forceinline__ void cp_async16(uint32_t dst, const void* src) {
    asm volatile("cp.async.ca.shared.global [%0], [%1], 16;\n" :: "r"(dst), "l"(src));
}
__device__ __forceinline__ void cp_commit() {
    asm volatile("cp.async.commit_group;\n");
}
template <int N>
__device__ __forceinline__ void cp_wait() {
    asm volatile("cp.async.wait_group %0;\n" :: "n"(N));
}

// ---------------------------------------------------------------------------
// Combined convert kernel: z fp32->bf16 | c fp32->bf16 | W transpose+convert
// grid: [0,4096) z, [4096,8192) c, [8192,9216) W
// ---------------------------------------------------------------------------
__global__ void k_convert_all(const float* __restrict__ z, const float* __restrict__ c,
                              const float* __restrict__ W) {
    int b = blockIdx.x;
    int tid = threadIdx.x;
    if (b < 8192) {
        const float* src = (b < 4096) ? z : c;
        __nv_bfloat16* dst = (b < 4096) ? g_zbf : g_cbf;
        int idx = (((b & 4095) * 256) + tid) * 4;
        float4 v = *(const float4*)(src + idx);
        *(__nv_bfloat162*)(dst + idx) = __floats2bfloat162_rn(v.x, v.y);
        *(__nv_bfloat162*)(dst + idx + 2) = __floats2bfloat162_rn(v.z, v.w);
    } else {
        int i = (b - 8192) * 256 + tid;     // 0 .. 262143
        int n = i >> 9;
        int p = i & 511;
        g_Wt[i] = __float2bfloat16(W[p * DD + n]);
    }
}

// ---------------------------------------------------------------------------
// GEMM1: c_proj = c @ W + b.  M=8192, N=512, K=512.  (exact R6 version)
// CTA tile 128x128, 256 thr (8 warps, warp tile 32x64), K-chunk 64, 2-stage.
// ---------------------------------------------------------------------------
#define G1_LD 72
#define G1_TILE_B (128 * G1_LD * 2)      // 18432
#define G1_STAGE_B (2 * G1_TILE_B)      // 36864
#define G1_SMEM (2 * G1_STAGE_B)        // 73728 -> 2 CTAs/SM

__global__ __launch_bounds__(256) void k_gemm1(const float* __restrict__ bias) {
    extern __shared__ char sm[];
    const int tid = threadIdx.x;
    const int w = tid >> 5;
    const int lane = tid & 31;
    const int wr = w >> 1;
    const int wc = w & 1;
    const int g = lane >> 2;
    const int t4 = lane & 3;
    const int m0 = blockIdx.x * 128;
    const int n0 = blockIdx.y * 128;

    float acc[2][8][4];
#pragma unroll
    for (int a = 0; a < 2; a++)
#pragma unroll
        for (int nt = 0; nt < 8; nt++)
#pragma unroll
            for (int e = 0; e < 4; e++) acc[a][nt][e] = 0.f;

    auto issue = [&](int kc, int st) {
        char* base = sm + st * G1_STAGE_B;
        uint32_t sa = smem_u32(base);
        uint32_t sb = sa + G1_TILE_B;
#pragma unroll
        for (int it = 0; it < 4; it++) {
            int idx = tid + it * 256;
            int r = idx >> 3, cu = idx & 7;
            cp_async16(sa + (r * G1_LD + cu * 8) * 2,
                       g_cbf + (size_t)(m0 + r) * DD + kc * 64 + cu * 8);
        }
#pragma unroll
        for (int it = 0; it < 4; it++) {
            int idx = tid + it * 256;
            int r = idx >> 3, cu = idx & 7;
            cp_async16(sb + (r * G1_LD + cu * 8) * 2,
                       g_Wt + (size_t)(n0 + r) * DD + kc * 64 + cu * 8);
        }
        cp_commit();
    };

    issue(0, 0);

    for (int kc = 0; kc < 8; kc++) {
        if (kc < 7) issue(kc + 1, (kc + 1) & 1);
        if (kc < 7) cp_wait<1>(); else cp_wait<0>();
        __syncthreads();
        char* base = sm + (kc & 1) * G1_STAGE_B;
        uint32_t sa = smem_u32(base);
        uint32_t sb = sa + G1_TILE_B;
#pragma unroll
        for (int ks = 0; ks < 4; ks++) {
            uint32_t af[2][4];
#pragma unroll
            for (int a = 0; a < 2; a++) {
                uint32_t addr = sa + ((wr * 32 + a * 16 + (lane & 15)) * G1_LD +
                                      ks * 16 + (lane >> 4) * 8) * 2;
                ldm_x4(af[a][0], af[a][1], af[a][2], af[a][3], addr);
            }
#pragma unroll
            for (int np = 0; np < 4; np++) {
                uint32_t b0, b1, b2, b3;
                uint32_t addr = sb + ((wc * 64 + np * 16 + ((lane >> 4) & 1) * 8 +
                                       (lane & 7)) * G1_LD +
                                      ks * 16 + ((lane >> 3) & 1) * 8) * 2;
                ldm_x4(b0, b1, b2, b3, addr);
#pragma unroll
                for (int a = 0; a < 2; a++) {
                    mma_bf16(acc[a][2 * np], af[a][0], af[a][1], af[a][2], af[a][3], b0, b1);
                    mma_bf16(acc[a][2 * np + 1], af[a][0], af[a][1], af[a][2], af[a][3], b2, b3);
                }
            }
        }
        __syncthreads();
    }

#pragma unroll
    for (int a = 0; a < 2; a++) {
        int r0 = m0 + wr * 32 + a * 16 + g;
#pragma unroll
        for (int nt = 0; nt < 8; nt++) {
            int col = n0 + wc * 64 + nt * 8 + t4 * 2;
            float bv0 = bias[col], bv1 = bias[col + 1];
            *(__nv_bfloat162*)(g_cproj + (size_t)r0 * DD + col) =
                __floats2bfloat162_rn(acc[a][nt][0] + bv0, acc[a][nt][1] + bv1);
            *(__nv_bfloat162*)(g_cproj + (size_t)(r0 + 8) * DD + col) =
                __floats2bfloat162_rn(acc[a][nt][2] + bv0, acc[a][nt][3] + bv1);
        }
    }
}

// ---------------------------------------------------------------------------
// Fused scores + LSE - diag (R6 structure + ks-level frag double buffering).
// Grid (49, 3): CTA = (t-pair {t0,t0+1}, s-window). 256 thr, 8 warps.
// C pair resident (M=128 x K=512, ld 520). Phase = 2 s-slots x 4 warps,
// warp tile 32x64. Z streamed in 128-col D-chunks, 2-stage x 2 slots.
// 1 CTA/SM (SMEM-bound) -> registers free: explicit A/B fragment double
// buffers give LDSM->use distance of a full 16-MMA block.
// ---------------------------------------------------------------------------
#define SC_LD 520
#define SC_BYTES (128 * SC_LD * 2)       // 133120
#define SZ_LD 136
#define SZ_SLOT (64 * SZ_LD * 2)         // 17408
#define SZ_BYTES (4 * SZ_SLOT)           // 69632
#define S_SMEM (SC_BYTES + SZ_BYTES + 64)  // 202816

__global__ __launch_bounds__(256) void k_scores() {
    extern __shared__ char sm[];
    uint32_t sC = smem_u32(sm);
    uint32_t sZ0 = sC + SC_BYTES;
    float* sRed = (float*)(sm + SC_BYTES + SZ_BYTES);

    const int t0 = blockIdx.x * 2;
    const int y = blockIdx.y;
    const int s_base = t0 + 1 + ((y == 0) ? 0 : (y == 1) ? 11 : 21);
    const int win = (y == 0) ? 11 : 10;
    const int P = (win + 1) >> 1;       // phases (2 s per phase; last may be 1)
    const int ITERS = 4 * P;

    const int tid = threadIdx.x;
    const int w = tid >> 5;
    const int lane = tid & 31;
    const int slot = w >> 2;            // s-slot within phase (0/1)
    const int wr = w & 3;               // row quarter: rows wr*32..+32 of M=128
    const int g = lane >> 2;
    const int t4 = lane & 3;

    // --- Prologue: C tiles for t0 and t0+1 (rows 0-63 / 64-127) ---
#pragma unroll
    for (int it = 0; it < 32; it++) {
        int idx = tid + it * 256;           // 0..8191 -> 128 rows x 64 uint4
        int r = idx >> 6, cu = idx & 63;
        int i = r & 63, tt = t0 + (r >> 6);
        cp_async16(sC + (r * SC_LD + cu * 8) * 2,
                   g_cproj + ((size_t)i * TT + tt) * DD + cu * 8);
    }
    cp_commit();

    auto issue_z = [&](int it) {
        int p = it >> 2, ch = it & 3, st = it & 1;
#pragma unroll
        for (int sl = 0; sl < 2; sl++) {
            if (2 * p + sl >= win) break;
            int s = s_base + 2 * p + sl;
            uint32_t dst = sZ0 + (uint32_t)(st * 2 + sl) * SZ_SLOT;
#pragma unroll
            for (int j = 0; j < 4; j++) {
                int idx = tid + j * 256;    // 0..1023 -> 64 rows x 16 uint4
                int r = idx >> 4, cu = idx & 15;
                cp_async16(dst + (r * SZ_LD + cu * 8) * 2,
                           g_zbf + ((size_t)r * TT + s) * DD + ch * 128 + cu * 8);
            }
        }
        cp_commit();
    };

    issue_z(0);
    issue_z(1);
    cp_wait<1>();       // C + stage0 ready
    __syncthreads();

    float acc[2][8][4];
#pragma unroll
    for (int a = 0; a < 2; a++)
#pragma unroll
        for (int nt = 0; nt < 8; nt++)
#pragma unroll
            for (int e = 0; e < 4; e++) acc[a][nt][e] = 0.f;

    for (int it = 0; it < ITERS; it++) {
        const int p = it >> 2, ch = it & 3;
        const bool slot_active = (2 * p + slot) < win;

        // --- Compute this D-chunk with ks-level fragment double buffering ---
        if (slot_active) {
            uint32_t sz = sZ0 + (uint32_t)((it & 1) * 2 + slot) * SZ_SLOT;

            uint32_t afA[2][2][4];          // [buf][a][reg]
            uint32_t bfB[2][4][4];          // [buf][np][reg]

            auto loadA = [&](int buf, int ks) {
#pragma unroll
                for (int a = 0; a < 2; a++) {
                    uint32_t addr = sC + ((wr * 32 + a * 16 + (lane & 15)) * SC_LD +
                                          ch * 128 + ks * 16 + (lane >> 4) * 8) * 2;
                    ldm_x4(afA[buf][a][0], afA[buf][a][1],
                           afA[buf][a][2], afA[buf][a][3], addr);
                }
            };
            auto loadB = [&](int buf, int ks) {
#pragma unroll
                for (int np = 0; np < 4; np++) {
                    uint32_t addr = sz + ((np * 16 + ((lane >> 4) & 1) * 8 +
                                           (lane & 7)) * SZ_LD +
                                          ks * 16 + ((lane >> 3) & 1) * 8) * 2;
                    ldm_x4(bfB[buf][np][0], bfB[buf][np][1],
                           bfB[buf][np][2], bfB[buf][np][3], addr);
                }
            };

            loadA(0, 0);
            loadB(0, 0);
#pragma unroll
            for (int ks = 0; ks < 8; ks++) {
                const int cur = ks & 1, nxt = cur ^ 1;
                if (ks < 7) {               // prefetch ks+1 while MMAing ks
                    loadA(nxt, ks + 1);
                    loadB(nxt, ks + 1);
                }
#pragma unroll
                for (int np = 0; np < 4; np++) {
#pragma unroll
                    for (int a = 0; a < 2; a++) {
                        mma_bf16(acc[a][2 * np],
                                 afA[cur][a][0], afA[cur][a][1],
                                 afA[cur][a][2], afA[cur][a][3],
                                 bfB[cur][np][0], bfB[cur][np][1]);
                        mma_bf16(acc[a][2 * np + 1],
                                 afA[cur][a][0], afA[cur][a][1],
                                 afA[cur][a][2], afA[cur][a][3],
                                 bfB[cur][np][2], bfB[cur][np][3]);
                    }
                }
            }
        }
        __syncthreads();                    // stage fully consumed

        if (it + 2 < ITERS) issue_z(it + 2);

        // --- End of phase: LSE - diag epilogue ---
        if (ch == 3) {
            const int s = s_base + 2 * p + slot;
            const int th = wr >> 1;         // row half: 0 -> t0, 1 -> t0+1
            const int tcur = t0 + th;
            const int k = s - tcur;
            const bool valid = slot_active && (k >= 1) && (k <= 30);

            float local = 0.f;
            if (valid) {
#pragma unroll
                for (int a = 0; a < 2; a++) {
#pragma unroll
                    for (int rp = 0; rp < 2; rp++) {
                        const int e0 = rp * 2;
                        float m = -3.4e38f;
#pragma unroll
                        for (int nt = 0; nt < 8; nt++)
                            m = fmaxf(m, fmaxf(acc[a][nt][e0], acc[a][nt][e0 + 1]));
                        m = fmaxf(m, __shfl_xor_sync(0xffffffffu, m, 1));
                        m = fmaxf(m, __shfl_xor_sync(0xffffffffu, m, 2));
                        float se = 0.f;
#pragma unroll
                        for (int nt = 0; nt < 8; nt++) {
                            se += expf((acc[a][nt][e0] - m) * INV_TEMP);
                            se += expf((acc[a][nt][e0 + 1] - m) * INV_TEMP);
                        }
                        se += __shfl_xor_sync(0xffffffffu, se, 1);
                        se += __shfl_xor_sync(0xffffffffu, se, 2);
                        float lse = m * INV_TEMP + logf(se);
                        int r = wr * 32 + a * 16 + rp * 8 + g;   // 0..127
                        int j = r & 63;                          // diag col
                        if (t4 == ((j >> 1) & 3))
                            local += lse - acc[a][j >> 3][e0 + (j & 1)] * INV_TEMP;
                    }
                }
            }
#pragma unroll
            for (int off = 16; off > 0; off >>= 1)
                local += __shfl_xor_sync(0xffffffffu, local, off);
            if (lane == 0) sRed[w] = local;
            __syncthreads();
            // sRed[w]: w = slot*4 + half*2 + {0,1}
            if (tid < 4) {
                int wsl = tid >> 1, half = tid & 1;
                if (2 * p + wsl < win) {
                    int ss = s_base + 2 * p + wsl;
                    int tt = t0 + half;
                    int kk = ss - tt;
                    if (kk >= 1 && kk <= 30)
                        g_partials[tt * HH + kk - 1] =
                            sRed[wsl * 4 + half * 2] + sRed[wsl * 4 + half * 2 + 1];
                }
            }
            // zero accumulators for next phase
#pragma unroll
            for (int a = 0; a < 2; a++)
#pragma unroll
                for (int nt = 0; nt < 8; nt++)
#pragma unroll
                    for (int e = 0; e < 4; e++) acc[a][nt][e] = 0.f;
        }

        if (it + 1 < ITERS) {
            if (it + 2 < ITERS) cp_wait<1>(); else cp_wait<0>();
            __syncthreads();                // next stage ready
        }
    }
}

// ---------------------------------------------------------------------------
// Final deterministic reduction — 1024 threads, two-level warp reduce.
// ---------------------------------------------------------------------------
__global__ void k_reduce(float* __restrict__ out) {
    __shared__ float sh[32];
    int tid = threadIdx.x;
    float ssum = 0.f;
#pragma unroll
    for (int i = 0; i < 3; i++) {
        int idx = tid + i * 1024;
        if (idx < TM * HH) ssum += g_partials[idx];
    }
#pragma unroll
    for (int off = 16; off > 0; off >>= 1)
        ssum += __shfl_xor_sync(0xffffffffu, ssum, off);
    if ((tid & 31) == 0) sh[tid >> 5] = ssum;
    __syncthreads();
    if (tid < 32) {
        float v = sh[tid];
#pragma unroll
        for (int off = 16; off > 0; off >>= 1)
            v += __shfl_xor_sync(0xffffffffu, v, off);
        if (tid == 0) out[0] = v / (float)(TM * HH * BB);
    }
}

// ---------------------------------------------------------------------------
extern "C" void kernel_launch(void* const* d_in, const int* in_sizes, int n_in,
                              void* d_out, int out_size) {
    const float* z = (const float*)d_in[0];
    const float* c = (const float*)d_in[1];
    const float* W = (const float*)d_in[2];
    const float* bias = (const float*)d_in[3];
    float* out = (float*)d_out;
    (void)in_sizes; (void)n_in; (void)out_size;

    cudaFuncSetAttribute(k_scores, cudaFuncAttributeMaxDynamicSharedMemorySize, S_SMEM);
    cudaFuncSetAttribute(k_gemm1, cudaFuncAttributeMaxDynamicSharedMemorySize, G1_SMEM);

    k_convert_all<<<9216, 256>>>(z, c, W);
    k_gemm1<<<dim3(64, 4), 256, G1_SMEM>>>(bias);
    k_scores<<<dim3(49, 3), 256, S_SMEM>>>();
    k_reduce<<<1, 1024>>>(out);
}

// round 16
// speedup vs baseline: 2.8083x; 1.0582x over previous
#include <cuda_runtime.h>
#include <cuda_bf16.h>
#include <cstdint>

// Problem constants
#define BB 64
#define TT 128
#define DD 512
#define HH 30
#define TM 98
static constexpr float INV_TEMP = 1.0f / 0.07f;

// Scratch (device globals: no allocation allowed)
__device__ __align__(16) __nv_bfloat16 g_zbf[BB * TT * DD];    // bf16 z_seq
__device__ __align__(16) __nv_bfloat16 g_cbf[BB * TT * DD];    // bf16 c_seq
__device__ __align__(16) __nv_bfloat16 g_cproj[BB * TT * DD];  // bf16 c_proj (t<98 valid)
__device__ __align__(16) __nv_bfloat16 g_Wt[DD * DD];          // bf16 W^T ([n][p])
__device__ float g_partials[TM * HH];
__device__ int g_count = 0;                                    // last-CTA counter

// ---------------------------------------------------------------------------
// PTX helpers
// ---------------------------------------------------------------------------
__device__ __forceinline__ uint32_t smem_u32(const void* p) {
    return (uint32_t)__cvta_generic_to_shared(p);
}
__device__ __forceinline__ void ldm_x4(uint32_t& a0, uint32_t& a1, uint32_t& a2,
                                       uint32_t& a3, uint32_t addr) {
    asm volatile("ldmatrix.sync.aligned.m8n8.x4.shared.b16 {%0,%1,%2,%3}, [%4];\n"
                 : "=r"(a0), "=r"(a1), "=r"(a2), "=r"(a3) : "r"(addr));
}
__device__ __forceinline__ void mma_bf16(float* c, uint32_t a0, uint32_t a1,
                                         uint32_t a2, uint32_t a3,
                                         uint32_t b0, uint32_t b1) {
    asm volatile(
        "mma.sync.aligned.m16n8k16.row.col.f32.bf16.bf16.f32 "
        "{%0,%1,%2,%3}, {%4,%5,%6,%7}, {%8,%9}, {%0,%1,%2,%3};\n"
        : "+f"(c[0]), "+f"(c[1]), "+f"(c[2]), "+f"(c[3])
        : "r"(a0), "r"(a1), "r"(a2), "r"(a3), "r"(b0), "r"(b1));
}
__device__ __forceinline__ void cp_async16(uint32_t dst, const void* src) {
    asm volatile("cp.async.ca.shared.global [%0], [%1], 16;\n" :: "r"(dst), "l"(src));
}
__device__ __forceinline__ void cp_commit() {
    asm volatile("cp.async.commit_group;\n");
}
template <int N>
__device__ __forceinline__ void cp_wait() {
    asm volatile("cp.async.wait_group %0;\n" :: "n"(N));
}

// ---------------------------------------------------------------------------
// Combined convert kernel:
//   [0,4096)    z fp32->bf16
//   [4096,8192) c fp32->bf16
//   [8192,8256) W transpose+convert via SMEM 64x64 tiles (coalesced both ways)
// ---------------------------------------------------------------------------
__global__ void k_convert_all(const float* __restrict__ z, const float* __restrict__ c,
                              const float* __restrict__ W) {
    int b = blockIdx.x;
    int tid = threadIdx.x;
    if (b < 8192) {
        const float* src = (b < 4096) ? z : c;
        __nv_bfloat16* dst = (b < 4096) ? g_zbf : g_cbf;
        int idx = (((b & 4095) * 256) + tid) * 4;
        float4 v = *(const float4*)(src + idx);
        *(__nv_bfloat162*)(dst + idx) = __floats2bfloat162_rn(v.x, v.y);
        *(__nv_bfloat162*)(dst + idx + 2) = __floats2bfloat162_rn(v.z, v.w);
    } else {
        __shared__ float tile[64][65];
        int tb = b - 8192;                  // 0..63 -> 8x8 tiles of 64x64
        int pBase = (tb >> 3) * 64;
        int nBase = (tb & 7) * 64;
        int tx = tid & 63, ty = tid >> 6;   // 64 x 4
#pragma unroll
        for (int i = 0; i < 16; i++) {
            int row = ty + i * 4;           // p-local
            tile[row][tx] = W[(pBase + row) * DD + nBase + tx];
        }
        __syncthreads();
#pragma unroll
        for (int i = 0; i < 16; i++) {
            int row = ty + i * 4;           // n-local
            g_Wt[(size_t)(nBase + row) * DD + pBase + tx] =
                __float2bfloat16(tile[tx][row]);
        }
    }
}

// ---------------------------------------------------------------------------
// GEMM1 (compacted): c_proj[b][t<98] = c[b][t] @ W + bias.
// Packed rows r = b*98 + t, M = 6272. CTA tile 64x128, 128 thr (4 warps,
// warp tile 32x64), K-chunk 64, cp.async 2-stage. Grid (98, 4) = 392 CTAs,
// 55.3 KB SMEM -> 4 CTAs/SM for wave smoothing.
// ---------------------------------------------------------------------------
#define G1_LD 72
#define G1_A_B (64 * G1_LD * 2)          // 9216
#define G1_B_B (128 * G1_LD * 2)         // 18432
#define G1_STAGE (G1_A_B + G1_B_B)       // 27648
#define G1_SMEM (2 * G1_STAGE)           // 55296

__global__ __launch_bounds__(128) void k_gemm1(const float* __restrict__ bias) {
    extern __shared__ char sm[];
    const int tid = threadIdx.x;
    const int w = tid >> 5;
    const int lane = tid & 31;
    const int wr = w >> 1;          // 0..1 : rows wr*32
    const int wc = w & 1;           // 0..1 : cols wc*64
    const int g = lane >> 2;
    const int t4 = lane & 3;
    const int m0 = blockIdx.x * 64;     // packed row base (r = b*98 + t)
    const int n0 = blockIdx.y * 128;

    float acc[2][8][4];
#pragma unroll
    for (int a = 0; a < 2; a++)
#pragma unroll
        for (int nt = 0; nt < 8; nt++)
#pragma unroll
            for (int e = 0; e < 4; e++) acc[a][nt][e] = 0.f;

    auto issue = [&](int kc, int st) {
        char* base = sm + st * G1_STAGE;
        uint32_t sa = smem_u32(base);
        uint32_t sb = sa + G1_A_B;
#pragma unroll
        for (int it = 0; it < 4; it++) {
            int idx = tid + it * 128;          // 0..511: 64 rows x 8 u4
            int r = idx >> 3, cu = idx & 7;
            int rg = m0 + r;
            int bb = rg / 98;
            int tt = rg - bb * 98;
            cp_async16(sa + (r * G1_LD + cu * 8) * 2,
                       g_cbf + ((size_t)bb * TT + tt) * DD + kc * 64 + cu * 8);
        }
#pragma unroll
        for (int it = 0; it < 8; it++) {
            int idx = tid + it * 128;          // 0..1023: 128 rows x 8 u4
            int r = idx >> 3, cu = idx & 7;
            cp_async16(sb + (r * G1_LD + cu * 8) * 2,
                       g_Wt + (size_t)(n0 + r) * DD + kc * 64 + cu * 8);
        }
        cp_commit();
    };

    issue(0, 0);

    for (int kc = 0; kc < 8; kc++) {
        if (kc < 7) issue(kc + 1, (kc + 1) & 1);
        if (kc < 7) cp_wait<1>(); else cp_wait<0>();
        __syncthreads();
        char* base = sm + (kc & 1) * G1_STAGE;
        uint32_t sa = smem_u32(base);
        uint32_t sb = sa + G1_A_B;
#pragma unroll
        for (int ks = 0; ks < 4; ks++) {
            uint32_t af[2][4];
#pragma unroll
            for (int a = 0; a < 2; a++) {
                uint32_t addr = sa + ((wr * 32 + a * 16 + (lane & 15)) * G1_LD +
                                      ks * 16 + (lane >> 4) * 8) * 2;
                ldm_x4(af[a][0], af[a][1], af[a][2], af[a][3], addr);
            }
#pragma unroll
            for (int np = 0; np < 4; np++) {
                uint32_t b0, b1, b2, b3;
                uint32_t addr = sb + ((wc * 64 + np * 16 + ((lane >> 4) & 1) * 8 +
                                       (lane & 7)) * G1_LD +
                                      ks * 16 + ((lane >> 3) & 1) * 8) * 2;
                ldm_x4(b0, b1, b2, b3, addr);
#pragma unroll
                for (int a = 0; a < 2; a++) {
                    mma_bf16(acc[a][2 * np], af[a][0], af[a][1], af[a][2], af[a][3], b0, b1);
                    mma_bf16(acc[a][2 * np + 1], af[a][0], af[a][1], af[a][2], af[a][3], b2, b3);
                }
            }
        }
        __syncthreads();
    }

    // Epilogue: bias + bf16 store with packed-row -> (b,t) scatter
#pragma unroll
    for (int a = 0; a < 2; a++) {
        int r0 = m0 + wr * 32 + a * 16 + g;
        int b0r = r0 / 98, t0r = r0 - b0r * 98;
        int r1 = r0 + 8;
        int b1r = r1 / 98, t1r = r1 - b1r * 98;
#pragma unroll
        for (int nt = 0; nt < 8; nt++) {
            int col = n0 + wc * 64 + nt * 8 + t4 * 2;
            float bv0 = bias[col], bv1 = bias[col + 1];
            *(__nv_bfloat162*)(g_cproj + ((size_t)b0r * TT + t0r) * DD + col) =
                __floats2bfloat162_rn(acc[a][nt][0] + bv0, acc[a][nt][1] + bv1);
            *(__nv_bfloat162*)(g_cproj + ((size_t)b1r * TT + t1r) * DD + col) =
                __floats2bfloat162_rn(acc[a][nt][2] + bv0, acc[a][nt][3] + bv1);
        }
    }
}

// ---------------------------------------------------------------------------
// Fused scores + LSE - diag (EXACT R14 compute) + last-CTA final reduction.
// Grid (49, 3): CTA = (t-pair {t0,t0+1}, s-window). 256 thr, 8 warps.
// ---------------------------------------------------------------------------
#define SC_LD 520
#define SC_BYTES (128 * SC_LD * 2)       // 133120
#define SZ_LD 136
#define SZ_SLOT (64 * SZ_LD * 2)         // 17408
#define SZ_BYTES (4 * SZ_SLOT)           // 69632
#define S_SMEM (SC_BYTES + SZ_BYTES + 64)  // 202816

__global__ __launch_bounds__(256) void k_scores(float* __restrict__ out) {
    extern __shared__ char sm[];
    uint32_t sC = smem_u32(sm);
    uint32_t sZ0 = sC + SC_BYTES;
    float* sRed = (float*)(sm + SC_BYTES + SZ_BYTES);   // 16 floats spare
    __shared__ int sLast;

    const int t0 = blockIdx.x * 2;
    const int y = blockIdx.y;
    const int s_base = t0 + 1 + ((y == 0) ? 0 : (y == 1) ? 11 : 21);
    const int win = (y == 0) ? 11 : 10;
    const int P = (win + 1) >> 1;
    const int ITERS = 4 * P;

    const int tid = threadIdx.x;
    const int w = tid >> 5;
    const int lane = tid & 31;
    const int slot = w >> 2;
    const int wr = w & 3;
    const int g = lane >> 2;
    const int t4 = lane & 3;

    // --- Prologue: C tiles for t0 and t0+1 ---
#pragma unroll
    for (int it = 0; it < 32; it++) {
        int idx = tid + it * 256;
        int r = idx >> 6, cu = idx & 63;
        int i = r & 63, tt = t0 + (r >> 6);
        cp_async16(sC + (r * SC_LD + cu * 8) * 2,
                   g_cproj + ((size_t)i * TT + tt) * DD + cu * 8);
    }
    cp_commit();

    auto issue_z = [&](int it) {
        int p = it >> 2, ch = it & 3, st = it & 1;
#pragma unroll
        for (int sl = 0; sl < 2; sl++) {
            if (2 * p + sl >= win) break;
            int s = s_base + 2 * p + sl;
            uint32_t dst = sZ0 + (uint32_t)(st * 2 + sl) * SZ_SLOT;
#pragma unroll
            for (int j = 0; j < 4; j++) {
                int idx = tid + j * 256;
                int r = idx >> 4, cu = idx & 15;
                cp_async16(dst + (r * SZ_LD + cu * 8) * 2,
                           g_zbf + ((size_t)r * TT + s) * DD + ch * 128 + cu * 8);
            }
        }
        cp_commit();
    };

    issue_z(0);
    issue_z(1);
    cp_wait<1>();
    __syncthreads();

    float acc[2][8][4];
#pragma unroll
    for (int a = 0; a < 2; a++)
#pragma unroll
        for (int nt = 0; nt < 8; nt++)
#pragma unroll
            for (int e = 0; e < 4; e++) acc[a][nt][e] = 0.f;

    for (int it = 0; it < ITERS; it++) {
        const int p = it >> 2, ch = it & 3;
        const bool slot_active = (2 * p + slot) < win;

        if (slot_active) {
            uint32_t sz = sZ0 + (uint32_t)((it & 1) * 2 + slot) * SZ_SLOT;
#pragma unroll
            for (int ks = 0; ks < 8; ks++) {
                uint32_t af[2][4];
#pragma unroll
                for (int a = 0; a < 2; a++) {
                    uint32_t addr = sC + ((wr * 32 + a * 16 + (lane & 15)) * SC_LD +
                                          ch * 128 + ks * 16 + (lane >> 4) * 8) * 2;
                    ldm_x4(af[a][0], af[a][1], af[a][2], af[a][3], addr);
                }
#pragma unroll
                for (int np = 0; np < 4; np++) {
                    uint32_t b0, b1, b2, b3;
                    uint32_t addr = sz + ((np * 16 + ((lane >> 4) & 1) * 8 +
                                           (lane & 7)) * SZ_LD +
                                          ks * 16 + ((lane >> 3) & 1) * 8) * 2;
                    ldm_x4(b0, b1, b2, b3, addr);
#pragma unroll
                    for (int a = 0; a < 2; a++) {
                        mma_bf16(acc[a][2 * np], af[a][0], af[a][1], af[a][2], af[a][3], b0, b1);
                        mma_bf16(acc[a][2 * np + 1], af[a][0], af[a][1], af[a][2], af[a][3], b2, b3);
                    }
                }
            }
        }
        __syncthreads();

        if (it + 2 < ITERS) issue_z(it + 2);

        if (ch == 3) {
            const int s = s_base + 2 * p + slot;
            const int th = wr >> 1;
            const int tcur = t0 + th;
            const int k = s - tcur;
            const bool valid = slot_active && (k >= 1) && (k <= 30);

            float local = 0.f;
            if (valid) {
#pragma unroll
                for (int a = 0; a < 2; a++) {
#pragma unroll
                    for (int rp = 0; rp < 2; rp++) {
                        const int e0 = rp * 2;
                        float m = -3.4e38f;
#pragma unroll
                        for (int nt = 0; nt < 8; nt++)
                            m = fmaxf(m, fmaxf(acc[a][nt][e0], acc[a][nt][e0 + 1]));
                        m = fmaxf(m, __shfl_xor_sync(0xffffffffu, m, 1));
                        m = fmaxf(m, __shfl_xor_sync(0xffffffffu, m, 2));
                        float se = 0.f;
#pragma unroll
                        for (int nt = 0; nt < 8; nt++) {
                            se += expf((acc[a][nt][e0] - m) * INV_TEMP);
                            se += expf((acc[a][nt][e0 + 1] - m) * INV_TEMP);
                        }
                        se += __shfl_xor_sync(0xffffffffu, se, 1);
                        se += __shfl_xor_sync(0xffffffffu, se, 2);
                        float lse = m * INV_TEMP + logf(se);
                        int r = wr * 32 + a * 16 + rp * 8 + g;
                        int j = r & 63;
                        if (t4 == ((j >> 1) & 3))
                            local += lse - acc[a][j >> 3][e0 + (j & 1)] * INV_TEMP;
                    }
                }
            }
#pragma unroll
            for (int off = 16; off > 0; off >>= 1)
                local += __shfl_xor_sync(0xffffffffu, local, off);
            if (lane == 0) sRed[w] = local;
            __syncthreads();
            if (tid < 4) {
                int wsl = tid >> 1, half = tid & 1;
                if (2 * p + wsl < win) {
                    int ss = s_base + 2 * p + wsl;
                    int tt = t0 + half;
                    int kk = ss - tt;
                    if (kk >= 1 && kk <= 30)
                        g_partials[tt * HH + kk - 1] =
                            sRed[wsl * 4 + half * 2] + sRed[wsl * 4 + half * 2 + 1];
                }
            }
#pragma unroll
            for (int a = 0; a < 2; a++)
#pragma unroll
                for (int nt = 0; nt < 8; nt++)
#pragma unroll
                    for (int e = 0; e < 4; e++) acc[a][nt][e] = 0.f;
        }

        if (it + 1 < ITERS) {
            if (it + 2 < ITERS) cp_wait<1>(); else cp_wait<0>();
            __syncthreads();
        }
    }

    // --- Last-CTA deterministic final reduction (replaces k_reduce launch) ---
    __threadfence();
    __syncthreads();
    if (tid == 0) sLast = (atomicAdd(&g_count, 1) == 49 * 3 - 1) ? 1 : 0;
    __syncthreads();
    if (sLast) {
        float ssum = 0.f;
        for (int i = tid; i < TM * HH; i += 256) ssum += g_partials[i];
#pragma unroll
        for (int off = 16; off > 0; off >>= 1)
            ssum += __shfl_xor_sync(0xffffffffu, ssum, off);
        if (lane == 0) sRed[w] = ssum;
        __syncthreads();
        if (tid == 0) {
            float tot = 0.f;
#pragma unroll
            for (int j = 0; j < 8; j++) tot += sRed[j];
            out[0] = tot / (float)(TM * HH * BB);
            g_count = 0;                    // reset for next graph replay
        }
    }
}

// ---------------------------------------------------------------------------
extern "C" void kernel_launch(void* const* d_in, const int* in_sizes, int n_in,
                              void* d_out, int out_size) {
    const float* z = (const float*)d_in[0];
    const float* c = (const float*)d_in[1];
    const float* W = (const float*)d_in[2];
    const float* bias = (const float*)d_in[3];
    float* out = (float*)d_out;
    (void)in_sizes; (void)n_in; (void)out_size;

    cudaFuncSetAttribute(k_scores, cudaFuncAttributeMaxDynamicSharedMemorySize, S_SMEM);
    cudaFuncSetAttribute(k_gemm1, cudaFuncAttributeMaxDynamicSharedMemorySize, G1_SMEM);

    k_convert_all<<<8256, 256>>>(z, c, W);
    k_gemm1<<<dim3(98, 4), 128, G1_SMEM>>>(bias);
    k_scores<<<dim3(49, 3), 256, S_SMEM>>>(out);
}